// round 4
// baseline (speedup 1.0000x reference)
#include <cuda_runtime.h>
#include <math.h>

// Problem constants
#define N0c 585728
#define N1c 22528
#define N2c 2048
#define E1c 563200
#define E2c 20480
#define INC 602
#define HIDc 256
#define OUTC 41

// ---------------- scratch (device globals; no allocation allowed) ----------
__device__ int   g_is64;
__device__ int   g_cnt1[N1c];
__device__ int   g_off1[N1c];
__device__ int   g_cur1[N1c];
__device__ int   g_srt1[E1c];
__device__ float g_agg1[N1c * INC];     // 54.2 MB
__device__ float g_h[N1c * HIDc];       // 23 MB
__device__ int   g_cnt2[N2c];
__device__ int   g_off2[N2c];
__device__ int   g_cur2[N2c];
__device__ int   g_srt2[E2c];
__device__ float g_agg2[N2c * HIDc];    // 2 MB

// ---------------- dtype detect: int64 vs int32 edge indices ----------------
// If buffer is int64 (values >=0, < 2^31), every odd 32-bit word is 0.
// If int32, odd words are real node ids (all-zero over 128 samples ~ impossible).
__global__ void k_detect(const int* __restrict__ e1) {
    if (threadIdx.x == 0 && blockIdx.x == 0) {
        int nz = 0;
        for (int i = 1; i < 256; i += 2) nz += (e1[i] != 0);
        g_is64 = (nz == 0) ? 1 : 0;
    }
}

__device__ __forceinline__ int edge_at(const void* ei, int E, int which, int e, int is64) {
    if (is64) return (int)((const long long*)ei)[(size_t)which * E + e];
    return ((const int*)ei)[(size_t)which * E + e];
}

// ---------------- zero histograms --------------------------------------------
__global__ void k_zero() {
    int i = blockIdx.x * blockDim.x + threadIdx.x;
    if (i < N1c) g_cnt1[i] = 0;
    if (i < N2c) g_cnt2[i] = 0;
}

// ---------------- histogram of dst -------------------------------------------
__global__ void k_count(const void* __restrict__ ei, int E, int* __restrict__ cnt) {
    int e = blockIdx.x * blockDim.x + threadIdx.x;
    if (e >= E) return;
    int is64 = g_is64;
    int d = edge_at(ei, E, 1, e, is64);
    atomicAdd(&cnt[d], 1);
}

// ---------------- single-block thread-coarsened exclusive scan ---------------
// Each thread serially scans its CH contiguous elements; one 1024-wide block
// scan over per-thread totals; then writeback. n <= 1024*CH required.
template <int CH>
__global__ void k_scan(const int* __restrict__ cnt, int* __restrict__ off,
                       int* __restrict__ cur, int n) {
    __shared__ int s[1024];
    int t = threadIdx.x;
    int base = t * CH;
    int loc[CH];
    int sum = 0;
#pragma unroll
    for (int j = 0; j < CH; j++) {
        int i = base + j;
        int v = (i < n) ? cnt[i] : 0;
        loc[j] = sum;          // local exclusive prefix
        sum += v;
    }
    s[t] = sum;
    __syncthreads();
#pragma unroll
    for (int st = 1; st < 1024; st <<= 1) {
        int v = (t >= st) ? s[t - st] : 0;
        __syncthreads();
        s[t] += v;
        __syncthreads();
    }
    int tbase = (t > 0) ? s[t - 1] : 0;   // exclusive prefix of this thread's chunk
#pragma unroll
    for (int j = 0; j < CH; j++) {
        int i = base + j;
        if (i < n) { int e = tbase + loc[j]; off[i] = e; cur[i] = e; }
    }
}

// ---------------- scatter src ids into dst-sorted order ----------------------
__global__ void k_scatter(const void* __restrict__ ei, int E,
                          int* __restrict__ cur, int* __restrict__ srt) {
    int e = blockIdx.x * blockDim.x + threadIdx.x;
    if (e >= E) return;
    int is64 = g_is64;
    int s = edge_at(ei, E, 0, e, is64);
    int d = edge_at(ei, E, 1, e, is64);
    int pos = atomicAdd(&cur[d], 1);
    srt[pos] = s;
}

// ---------------- per-dst mean aggregation (one block per dst row) -----------
template <int C>
__global__ void k_aggregate(const float* __restrict__ X, const int* __restrict__ off,
                            const int* __restrict__ cnt, const int* __restrict__ srt,
                            float* __restrict__ agg) {
    constexpr int NA = (C + 255) / 256;
    __shared__ int s_src[256];
    int row = blockIdx.x;
    int beg = off[row], deg = cnt[row];
    float acc[NA];
#pragma unroll
    for (int j = 0; j < NA; j++) acc[j] = 0.f;
    for (int t0 = 0; t0 < deg; t0 += 256) {
        int nn = min(256, deg - t0);
        __syncthreads();
        if ((int)threadIdx.x < nn) s_src[threadIdx.x] = srt[beg + t0 + threadIdx.x];
        __syncthreads();
#pragma unroll 4
        for (int i = 0; i < nn; i++) {
            const float* xr = X + (size_t)s_src[i] * C;
#pragma unroll
            for (int j = 0; j < NA; j++) {
                int c = threadIdx.x + j * 256;
                if (c < C) acc[j] += __ldg(xr + c);
            }
        }
    }
    float inv = deg > 0 ? 1.f / (float)deg : 0.f;
    float* ar = agg + (size_t)row * C;
#pragma unroll
    for (int j = 0; j < NA; j++) {
        int c = threadIdx.x + j * 256;
        if (c < C) ar[c] = acc[j] * inv;
    }
}

// ---------------- layer-1 fused dual GEMM + bias + ReLU ----------------------
// h[M,256] = relu(agg1[M,602]@Wl1[602,256] + x[M,602]@Wr1[602,256] + bl1)
// BM=128, BN=128, BK=8, 256 threads, 8x8 per thread.
__global__ void __launch_bounds__(256, 2)
k_gemm1(const float* __restrict__ A1x,     // x (phase 1 A)
        const float* __restrict__ B0,      // Wl1
        const float* __restrict__ B1,      // Wr1
        const float* __restrict__ bias,    // bl1
        float* __restrict__ C) {           // g_h
    __shared__ float As[8][132];           // +4 pad: conflict-free transposed store
    __shared__ float Bs[8][128];
    const int m0 = blockIdx.x * 128;
    const int n0 = blockIdx.y * 128;
    const int tid = threadIdx.x;
    const int tx = tid & 15, ty = tid >> 4;

    float acc[8][8];
#pragma unroll
    for (int i = 0; i < 8; i++)
#pragma unroll
        for (int j = 0; j < 8; j++) acc[i][j] = 0.f;

    for (int phase = 0; phase < 2; phase++) {
        const float* A = phase ? A1x : g_agg1;
        const float* B = phase ? B1 : B0;
        for (int k0 = 0; k0 < INC; k0 += 8) {
            // A tile: thread loads (m = p*32 + tid/8, k = tid%8)
            {
                int k = tid & 7;
                int mm = tid >> 3;
                bool okk = (k0 + k) < INC;
#pragma unroll
                for (int p = 0; p < 4; p++) {
                    int m = p * 32 + mm;
                    As[k][m] = okk ? A[(size_t)(m0 + m) * INC + k0 + k] : 0.f;
                }
            }
            // B tile: thread loads float4 at (kk = tid/32, n = (tid%32)*4)
            {
                int kk = tid >> 5;
                int n = (tid & 31) * 4;
                float4 v = make_float4(0.f, 0.f, 0.f, 0.f);
                if (k0 + kk < INC)
                    v = *(const float4*)&B[(size_t)(k0 + kk) * HIDc + n0 + n];
                *(float4*)&Bs[kk][n] = v;
            }
            __syncthreads();
#pragma unroll
            for (int k = 0; k < 8; k++) {
                float4 a0 = *(const float4*)&As[k][ty * 8];
                float4 a1 = *(const float4*)&As[k][ty * 8 + 4];
                float4 b0 = *(const float4*)&Bs[k][tx * 8];
                float4 b1 = *(const float4*)&Bs[k][tx * 8 + 4];
                float a[8] = {a0.x, a0.y, a0.z, a0.w, a1.x, a1.y, a1.z, a1.w};
                float b[8] = {b0.x, b0.y, b0.z, b0.w, b1.x, b1.y, b1.z, b1.w};
#pragma unroll
                for (int i = 0; i < 8; i++)
#pragma unroll
                    for (int j = 0; j < 8; j++) acc[i][j] = fmaf(a[i], b[j], acc[i][j]);
            }
            __syncthreads();
        }
    }
    // epilogue: + bias, ReLU
#pragma unroll
    for (int i = 0; i < 8; i++) {
        int m = m0 + ty * 8 + i;
#pragma unroll
        for (int j = 0; j < 8; j += 4) {
            int n = n0 + tx * 8 + j;
            float4 o;
            o.x = fmaxf(acc[i][j + 0] + bias[n + 0], 0.f);
            o.y = fmaxf(acc[i][j + 1] + bias[n + 1], 0.f);
            o.z = fmaxf(acc[i][j + 2] + bias[n + 2], 0.f);
            o.w = fmaxf(acc[i][j + 3] + bias[n + 3], 0.f);
            *(float4*)&C[(size_t)m * HIDc + n] = o;
        }
    }
}

// ---------------- layer-2 GEMM + bias + log_softmax (one block per row) ------
__global__ void k_out(const float* __restrict__ Wl2, const float* __restrict__ Wr2,
                      const float* __restrict__ bl2, float* __restrict__ out) {
    __shared__ float sa[HIDc];
    __shared__ float sh[HIDc];
    __shared__ float vals[OUTC];
    __shared__ float s_max, s_lse;
    int r = blockIdx.x;
    for (int c = threadIdx.x; c < HIDc; c += blockDim.x) {
        sa[c] = g_agg2[(size_t)r * HIDc + c];
        sh[c] = g_h[(size_t)r * HIDc + c];
    }
    __syncthreads();
    int n = threadIdx.x;
    if (n < OUTC) {
        float acc = bl2[n];
#pragma unroll 4
        for (int k = 0; k < HIDc; k++)
            acc += sa[k] * Wl2[k * OUTC + n] + sh[k] * Wr2[k * OUTC + n];
        vals[n] = acc;
    }
    __syncthreads();
    if (threadIdx.x == 0) {
        float mx = -1e30f;
        for (int i = 0; i < OUTC; i++) mx = fmaxf(mx, vals[i]);
        float s = 0.f;
        for (int i = 0; i < OUTC; i++) s += expf(vals[i] - mx);
        s_max = mx;
        s_lse = logf(s);
    }
    __syncthreads();
    if (n < OUTC) out[(size_t)r * OUTC + n] = vals[n] - s_max - s_lse;
}

// ---------------- launch -----------------------------------------------------
extern "C" void kernel_launch(void* const* d_in, const int* in_sizes, int n_in,
                              void* d_out, int out_size) {
    const float* x   = (const float*)d_in[0];
    const void*  ei1 = d_in[1];
    const void*  ei2 = d_in[2];
    const float* Wl1 = (const float*)d_in[3];
    const float* bl1 = (const float*)d_in[4];
    const float* Wr1 = (const float*)d_in[5];
    const float* Wl2 = (const float*)d_in[6];
    const float* bl2 = (const float*)d_in[7];
    const float* Wr2 = (const float*)d_in[8];
    float* out = (float*)d_out;

    // symbol addresses for generic kernels (host-side lookup; not a stream op)
    void *p_cnt1, *p_off1, *p_cur1, *p_srt1, *p_agg1, *p_h;
    void *p_cnt2, *p_off2, *p_cur2, *p_srt2, *p_agg2;
    cudaGetSymbolAddress(&p_cnt1, g_cnt1);
    cudaGetSymbolAddress(&p_off1, g_off1);
    cudaGetSymbolAddress(&p_cur1, g_cur1);
    cudaGetSymbolAddress(&p_srt1, g_srt1);
    cudaGetSymbolAddress(&p_agg1, g_agg1);
    cudaGetSymbolAddress(&p_h,    g_h);
    cudaGetSymbolAddress(&p_cnt2, g_cnt2);
    cudaGetSymbolAddress(&p_off2, g_off2);
    cudaGetSymbolAddress(&p_cur2, g_cur2);
    cudaGetSymbolAddress(&p_srt2, g_srt2);
    cudaGetSymbolAddress(&p_agg2, g_agg2);

    k_detect<<<1, 32>>>((const int*)ei1);
    k_zero<<<(N1c + 255) / 256, 256>>>();

    k_count<<<(E1c + 255) / 256, 256>>>(ei1, E1c, (int*)p_cnt1);
    k_count<<<(E2c + 255) / 256, 256>>>(ei2, E2c, (int*)p_cnt2);

    k_scan<22><<<1, 1024>>>((const int*)p_cnt1, (int*)p_off1, (int*)p_cur1, N1c);
    k_scan<2><<<1, 1024>>>((const int*)p_cnt2, (int*)p_off2, (int*)p_cur2, N2c);

    k_scatter<<<(E1c + 255) / 256, 256>>>(ei1, E1c, (int*)p_cur1, (int*)p_srt1);
    k_scatter<<<(E2c + 255) / 256, 256>>>(ei2, E2c, (int*)p_cur2, (int*)p_srt2);

    // layer-1 mean aggregation of 602-dim x rows
    k_aggregate<INC><<<N1c, 256>>>(x, (const int*)p_off1, (const int*)p_cnt1,
                                   (const int*)p_srt1, (float*)p_agg1);

    // layer-1 fused dual GEMM + ReLU -> g_h
    dim3 g1(N1c / 128, HIDc / 128);
    k_gemm1<<<g1, 256>>>(x, Wl1, Wr1, bl1, (float*)p_h);

    // layer-2 mean aggregation of 256-dim h rows
    k_aggregate<HIDc><<<N2c, 256>>>((const float*)p_h, (const int*)p_off2,
                                    (const int*)p_cnt2, (const int*)p_srt2,
                                    (float*)p_agg2);

    // layer-2 GEMM + bias + log_softmax
    k_out<<<N2c, 64>>>(Wl2, Wr2, bl2, out);
}

// round 6
// speedup vs baseline: 1.9910x; 1.9910x over previous
#include <cuda_runtime.h>
#include <cuda_fp16.h>
#include <math.h>
#include <stdint.h>

// Problem constants
#define N0c 585728
#define N1c 22528
#define N2c 2048
#define E1c 563200
#define E2c 20480
#define INC 602
#define HIDc 256
#define OUTC 41
#define KPAD 640            // per-operand K padded
#define KPAD2 1280          // concatenated K
#define BKc 64              // GEMM K tile
#define NITER (KPAD2 / BKc) // 20

// ---------------- scratch (device globals; no allocation allowed) ----------
__device__ int    g_is64;
__device__ int    g_cnt1[N1c];
__device__ int    g_off1[N1c];
__device__ int    g_cur1[N1c];
__device__ int    g_srt1[E1c];
__device__ __half g_acat[(size_t)N1c * KPAD2];  // [agg | x] fp16, 57.7 MB
__device__ __half g_bcat[(size_t)HIDc * KPAD2]; // [Wl;Wr]^T as [N=256][K=1280] fp16
__device__ float  g_h[(size_t)N1c * HIDc];      // 23 MB hidden (fp32)
__device__ int    g_cnt2[N2c];
__device__ int    g_off2[N2c];
__device__ int    g_cur2[N2c];
__device__ int    g_srt2[E2c];
__device__ float  g_agg2[(size_t)N2c * HIDc];   // 2 MB

// ======================= PTX helpers =======================================
__device__ __forceinline__ uint32_t smem_u32(const void* p) {
    uint32_t a;
    asm("{ .reg .u64 t; cvta.to.shared.u64 t, %1; cvt.u32.u64 %0, t; }" : "=r"(a) : "l"(p));
    return a;
}
#define CP_ASYNC16(sa, g) \
    asm volatile("cp.async.cg.shared.global [%0], [%1], 16;" :: "r"((uint32_t)(sa)), "l"(g))
#define CP_ASYNC_COMMIT() asm volatile("cp.async.commit_group;" ::: "memory")
#define CP_ASYNC_WAIT(n) asm volatile("cp.async.wait_group %0;" :: "n"(n) : "memory")
#define SWZ128(o) ((o) ^ (((o) >> 3) & 0x70))

__device__ __forceinline__ void ldsm_x4(uint32_t& r0, uint32_t& r1, uint32_t& r2,
                                        uint32_t& r3, uint32_t a) {
    asm volatile("ldmatrix.sync.aligned.m8n8.x4.shared.b16 {%0,%1,%2,%3}, [%4];"
                 : "=r"(r0), "=r"(r1), "=r"(r2), "=r"(r3) : "r"(a));
}
__device__ __forceinline__ void mma_16816(float* c, const uint32_t* a, const uint32_t* b) {
    asm volatile("mma.sync.aligned.m16n8k16.row.col.f32.f16.f16.f32 "
                 "{%0,%1,%2,%3}, {%4,%5,%6,%7}, {%8,%9}, {%0,%1,%2,%3};"
                 : "+f"(c[0]), "+f"(c[1]), "+f"(c[2]), "+f"(c[3])
                 : "r"(a[0]), "r"(a[1]), "r"(a[2]), "r"(a[3]), "r"(b[0]), "r"(b[1]));
}

// ---------------- dtype detect: int64 vs int32 edge indices ----------------
__global__ void k_detect(const int* __restrict__ e1) {
    if (threadIdx.x == 0 && blockIdx.x == 0) {
        int nz = 0;
        for (int i = 1; i < 256; i += 2) nz += (e1[i] != 0);
        g_is64 = (nz == 0) ? 1 : 0;
    }
}
__device__ __forceinline__ int edge_at(const void* ei, int E, int which, int e, int is64) {
    if (is64) return (int)((const long long*)ei)[(size_t)which * E + e];
    return ((const int*)ei)[(size_t)which * E + e];
}

__global__ void k_zero() {
    int i = blockIdx.x * blockDim.x + threadIdx.x;
    if (i < N1c) g_cnt1[i] = 0;
    if (i < N2c) g_cnt2[i] = 0;
}

__global__ void k_count(const void* __restrict__ ei, int E, int* __restrict__ cnt) {
    int e = blockIdx.x * blockDim.x + threadIdx.x;
    if (e >= E) return;
    int d = edge_at(ei, E, 1, e, g_is64);
    atomicAdd(&cnt[d], 1);
}

// ---------------- single-block thread-coarsened exclusive scan ---------------
template <int CH>
__global__ void k_scan(const int* __restrict__ cnt, int* __restrict__ off,
                       int* __restrict__ cur, int n) {
    __shared__ int s[1024];
    int t = threadIdx.x;
    int base = t * CH;
    int loc[CH];
    int sum = 0;
#pragma unroll
    for (int j = 0; j < CH; j++) {
        int i = base + j;
        int v = (i < n) ? cnt[i] : 0;
        loc[j] = sum;
        sum += v;
    }
    s[t] = sum;
    __syncthreads();
#pragma unroll
    for (int st = 1; st < 1024; st <<= 1) {
        int v = (t >= st) ? s[t - st] : 0;
        __syncthreads();
        s[t] += v;
        __syncthreads();
    }
    int tbase = (t > 0) ? s[t - 1] : 0;
#pragma unroll
    for (int j = 0; j < CH; j++) {
        int i = base + j;
        if (i < n) { int e = tbase + loc[j]; off[i] = e; cur[i] = e; }
    }
}

__global__ void k_scatter(const void* __restrict__ ei, int E,
                          int* __restrict__ cur, int* __restrict__ srt) {
    int e = blockIdx.x * blockDim.x + threadIdx.x;
    if (e >= E) return;
    int is64 = g_is64;
    int s = edge_at(ei, E, 0, e, is64);
    int d = edge_at(ei, E, 1, e, is64);
    int pos = atomicAdd(&cur[d], 1);
    srt[pos] = s;
}

// ---------------- layer-1 mean aggregation -> fp16 into acat[0:640] ----------
__global__ void k_aggregate1(const float* __restrict__ X, const int* __restrict__ off,
                             const int* __restrict__ cnt, const int* __restrict__ srt,
                             __half* __restrict__ acat) {
    __shared__ int s_src[256];
    int row = blockIdx.x;
    int beg = off[row], deg = cnt[row];
    float acc[3] = {0.f, 0.f, 0.f};
    for (int t0 = 0; t0 < deg; t0 += 256) {
        int nn = min(256, deg - t0);
        __syncthreads();
        if ((int)threadIdx.x < nn) s_src[threadIdx.x] = srt[beg + t0 + threadIdx.x];
        __syncthreads();
#pragma unroll 4
        for (int i = 0; i < nn; i++) {
            const float* xr = X + (size_t)s_src[i] * INC;
#pragma unroll
            for (int j = 0; j < 3; j++) {
                int c = threadIdx.x + j * 256;
                if (c < INC) acc[j] += __ldg(xr + c);
            }
        }
    }
    float inv = deg > 0 ? 1.f / (float)deg : 0.f;
    __half* ar = acat + (size_t)row * KPAD2;
#pragma unroll
    for (int j = 0; j < 3; j++) {
        int c = threadIdx.x + j * 256;
        if (c < INC) ar[c] = __float2half_rn(acc[j] * inv);
        else if (c < KPAD) ar[c] = __float2half_rn(0.f);
    }
}

// ---------------- fp16 conversions ------------------------------------------
__global__ void k_prep_x(const float* __restrict__ x, __half* __restrict__ acat) {
    int r = blockIdx.x;
    __half* ar = acat + (size_t)r * KPAD2 + KPAD;
    for (int c = threadIdx.x; c < KPAD; c += blockDim.x)
        ar[c] = (c < INC) ? __float2half_rn(x[(size_t)r * INC + c]) : __float2half_rn(0.f);
}
__global__ void k_prep_w(const float* __restrict__ Wl, const float* __restrict__ Wr,
                         __half* __restrict__ bcat) {
    int n = blockIdx.x;  // 0..255
    __half* br = bcat + (size_t)n * KPAD2;
    for (int k = threadIdx.x; k < KPAD2; k += blockDim.x) {
        float v = 0.f;
        if (k < INC) v = Wl[(size_t)k * HIDc + n];
        else if (k >= KPAD && k < KPAD + INC) v = Wr[(size_t)(k - KPAD) * HIDc + n];
        br[k] = __float2half_rn(v);
    }
}

// ---------------- layer-1 GEMM via mma.sync (fp16 in, fp32 acc) --------------
// H[M,256] = relu(acat[M,1280] @ bcat^T + bias), bcat is [N][K] row-major.
// BM=128, BN=64, BK=64; 8 warps, warp tile 32x32 (2 m-frags x 4 n-frags).
#define A_STAGE 16384            // 128 rows * 128 B
#define B_STAGE 8192             // 64 rows * 128 B
__global__ void __launch_bounds__(256)
k_gemm1_mma(const __half* __restrict__ A, const __half* __restrict__ B,
            const float* __restrict__ bias, float* __restrict__ H) {
    __shared__ char sm[2 * A_STAGE + 2 * B_STAGE];   // 48 KB
    const uint32_t sA = smem_u32(sm);
    const uint32_t sB = sA + 2 * A_STAGE;
    const int tid = threadIdx.x;
    const int lane = tid & 31, wid = tid >> 5;
    const int m0 = blockIdx.x * 128;
    const int n0 = blockIdx.y * 64;
    const int wm = (wid & 3) * 32;       // warp m offset in tile
    const int wn = (wid >> 2) * 32;      // warp n offset in tile

    // ---- cp.async load helpers (per-iteration) ----
    auto load_stage = [&](int it, int buf) {
        const size_t kbase = (size_t)it * BKc;
#pragma unroll
        for (int r = 0; r < 4; r++) {            // A: 1024 units of 16B
            int u = tid + r * 256;
            int row = u >> 3, un = u & 7;
            uint32_t so = SWZ128((uint32_t)(row * 128 + un * 16));
            const __half* g = A + (size_t)(m0 + row) * KPAD2 + kbase + un * 8;
            CP_ASYNC16(sA + buf * A_STAGE + so, (const char*)g);
        }
#pragma unroll
        for (int r = 0; r < 2; r++) {            // B: 512 units of 16B
            int u = tid + r * 256;
            int row = u >> 3, un = u & 7;
            uint32_t so = SWZ128((uint32_t)(row * 128 + un * 16));
            const __half* g = B + (size_t)(n0 + row) * KPAD2 + kbase + un * 8;
            CP_ASYNC16(sB + buf * B_STAGE + so, (const char*)g);
        }
        CP_ASYNC_COMMIT();
    };

    // ---- precomputed swizzled ldmatrix addresses (buf 0) ----
    uint32_t a_addr[2][4], b_addr[2][4];
#pragma unroll
    for (int mi = 0; mi < 2; mi++)
#pragma unroll
        for (int ks = 0; ks < 4; ks++) {
            int row = wm + mi * 16 + (lane & 15);
            int col = ks * 32 + ((lane >> 4) & 1) * 16;
            a_addr[mi][ks] = sA + SWZ128((uint32_t)(row * 128 + col));
        }
#pragma unroll
    for (int p = 0; p < 2; p++)
#pragma unroll
        for (int ks = 0; ks < 4; ks++) {
            int row = wn + p * 16 + ((lane >> 4) & 1) * 8 + (lane & 7);
            int col = ks * 32 + ((lane >> 3) & 1) * 16;
            b_addr[p][ks] = sB + SWZ128((uint32_t)(row * 128 + col));
        }

    float acc[2][4][4];
#pragma unroll
    for (int i = 0; i < 2; i++)
#pragma unroll
        for (int j = 0; j < 4; j++)
#pragma unroll
            for (int q = 0; q < 4; q++) acc[i][j][q] = 0.f;

    load_stage(0, 0);
    for (int it = 0; it < NITER; it++) {
        int buf = it & 1;
        if (it + 1 < NITER) {
            load_stage(it + 1, (it + 1) & 1);
            CP_ASYNC_WAIT(1);
        } else {
            CP_ASYNC_WAIT(0);
        }
        __syncthreads();

        uint32_t aoff = buf * A_STAGE, boff = buf * B_STAGE;
#pragma unroll
        for (int ks = 0; ks < 4; ks++) {
            uint32_t af[2][4];
#pragma unroll
            for (int mi = 0; mi < 2; mi++)
                ldsm_x4(af[mi][0], af[mi][1], af[mi][2], af[mi][3], a_addr[mi][ks] + aoff);
            uint32_t bf[4][2];
#pragma unroll
            for (int p = 0; p < 2; p++) {
                uint32_t r0, r1, r2, r3;
                ldsm_x4(r0, r1, r2, r3, b_addr[p][ks] + boff);
                bf[p * 2 + 0][0] = r0; bf[p * 2 + 0][1] = r1;
                bf[p * 2 + 1][0] = r2; bf[p * 2 + 1][1] = r3;
            }
#pragma unroll
            for (int mi = 0; mi < 2; mi++)
#pragma unroll
                for (int ni = 0; ni < 4; ni++)
                    mma_16816(acc[mi][ni], af[mi], bf[ni]);
        }
        __syncthreads();
    }

    // ---- epilogue: bias + ReLU, write fp32 H ----
#pragma unroll
    for (int mi = 0; mi < 2; mi++) {
#pragma unroll
        for (int ni = 0; ni < 4; ni++) {
            int col = n0 + wn + ni * 8 + (lane & 3) * 2;
            float b0 = __ldg(bias + col), b1 = __ldg(bias + col + 1);
            int r0 = m0 + wm + mi * 16 + (lane >> 2);
            float2 o0, o1;
            o0.x = fmaxf(acc[mi][ni][0] + b0, 0.f);
            o0.y = fmaxf(acc[mi][ni][1] + b1, 0.f);
            o1.x = fmaxf(acc[mi][ni][2] + b0, 0.f);
            o1.y = fmaxf(acc[mi][ni][3] + b1, 0.f);
            *(float2*)&H[(size_t)r0 * HIDc + col] = o0;
            *(float2*)&H[(size_t)(r0 + 8) * HIDc + col] = o1;
        }
    }
}

// ---------------- layer-2 mean aggregation (fp32) ----------------------------
__global__ void k_aggregate2(const float* __restrict__ X, const int* __restrict__ off,
                             const int* __restrict__ cnt, const int* __restrict__ srt,
                             float* __restrict__ agg) {
    __shared__ int s_src[256];
    int row = blockIdx.x;
    int beg = off[row], deg = cnt[row];
    float acc = 0.f;
    for (int t0 = 0; t0 < deg; t0 += 256) {
        int nn = min(256, deg - t0);
        __syncthreads();
        if ((int)threadIdx.x < nn) s_src[threadIdx.x] = srt[beg + t0 + threadIdx.x];
        __syncthreads();
#pragma unroll 4
        for (int i = 0; i < nn; i++)
            acc += __ldg(X + (size_t)s_src[i] * HIDc + threadIdx.x);
    }
    float inv = deg > 0 ? 1.f / (float)deg : 0.f;
    agg[(size_t)row * HIDc + threadIdx.x] = acc * inv;
}

// ---------------- layer-2 GEMM + bias + log_softmax --------------------------
__global__ void k_out(const float* __restrict__ Wl2, const float* __restrict__ Wr2,
                      const float* __restrict__ bl2, float* __restrict__ out) {
    __shared__ float sa[HIDc];
    __shared__ float sh[HIDc];
    __shared__ float vals[OUTC];
    __shared__ float s_max, s_lse;
    int r = blockIdx.x;
    for (int c = threadIdx.x; c < HIDc; c += blockDim.x) {
        sa[c] = g_agg2[(size_t)r * HIDc + c];
        sh[c] = g_h[(size_t)r * HIDc + c];
    }
    __syncthreads();
    int n = threadIdx.x;
    if (n < OUTC) {
        float acc = bl2[n];
#pragma unroll 4
        for (int k = 0; k < HIDc; k++)
            acc += sa[k] * Wl2[k * OUTC + n] + sh[k] * Wr2[k * OUTC + n];
        vals[n] = acc;
    }
    __syncthreads();
    if (threadIdx.x == 0) {
        float mx = -1e30f;
        for (int i = 0; i < OUTC; i++) mx = fmaxf(mx, vals[i]);
        float s = 0.f;
        for (int i = 0; i < OUTC; i++) s += expf(vals[i] - mx);
        s_max = mx;
        s_lse = logf(s);
    }
    __syncthreads();
    if (n < OUTC) out[(size_t)r * OUTC + n] = vals[n] - s_max - s_lse;
}

// ---------------- launch -----------------------------------------------------
extern "C" void kernel_launch(void* const* d_in, const int* in_sizes, int n_in,
                              void* d_out, int out_size) {
    const float* x   = (const float*)d_in[0];
    const void*  ei1 = d_in[1];
    const void*  ei2 = d_in[2];
    const float* Wl1 = (const float*)d_in[3];
    const float* bl1 = (const float*)d_in[4];
    const float* Wr1 = (const float*)d_in[5];
    const float* Wl2 = (const float*)d_in[6];
    const float* bl2 = (const float*)d_in[7];
    const float* Wr2 = (const float*)d_in[8];
    float* out = (float*)d_out;

    void *p_cnt1, *p_off1, *p_cur1, *p_srt1, *p_acat, *p_bcat, *p_h;
    void *p_cnt2, *p_off2, *p_cur2, *p_srt2, *p_agg2;
    cudaGetSymbolAddress(&p_cnt1, g_cnt1);
    cudaGetSymbolAddress(&p_off1, g_off1);
    cudaGetSymbolAddress(&p_cur1, g_cur1);
    cudaGetSymbolAddress(&p_srt1, g_srt1);
    cudaGetSymbolAddress(&p_acat, g_acat);
    cudaGetSymbolAddress(&p_bcat, g_bcat);
    cudaGetSymbolAddress(&p_h,    g_h);
    cudaGetSymbolAddress(&p_cnt2, g_cnt2);
    cudaGetSymbolAddress(&p_off2, g_off2);
    cudaGetSymbolAddress(&p_cur2, g_cur2);
    cudaGetSymbolAddress(&p_srt2, g_srt2);
    cudaGetSymbolAddress(&p_agg2, g_agg2);

    k_detect<<<1, 32>>>((const int*)ei1);
    k_zero<<<(N1c + 255) / 256, 256>>>();

    k_count<<<(E1c + 255) / 256, 256>>>(ei1, E1c, (int*)p_cnt1);
    k_count<<<(E2c + 255) / 256, 256>>>(ei2, E2c, (int*)p_cnt2);

    k_scan<22><<<1, 1024>>>((const int*)p_cnt1, (int*)p_off1, (int*)p_cur1, N1c);
    k_scan<2><<<1, 1024>>>((const int*)p_cnt2, (int*)p_off2, (int*)p_cur2, N2c);

    k_scatter<<<(E1c + 255) / 256, 256>>>(ei1, E1c, (int*)p_cur1, (int*)p_srt1);
    k_scatter<<<(E2c + 255) / 256, 256>>>(ei2, E2c, (int*)p_cur2, (int*)p_srt2);

    // fp16 conversions (weights + dst features into concat buffers)
    k_prep_w<<<HIDc, 256>>>(Wl1, Wr1, (__half*)p_bcat);
    k_prep_x<<<N1c, 256>>>(x, (__half*)p_acat);

    // layer-1 mean aggregation (fp32 acc -> fp16 out, K-padded, into acat[0:640])
    k_aggregate1<<<N1c, 256>>>(x, (const int*)p_off1, (const int*)p_cnt1,
                               (const int*)p_srt1, (__half*)p_acat);

    // layer-1 fused dual GEMM + bias + ReLU via mma.sync -> g_h (fp32)
    dim3 gg(N1c / 128, HIDc / 64);
    k_gemm1_mma<<<gg, 256>>>((const __half*)p_acat, (const __half*)p_bcat, bl1, (float*)p_h);

    // layer-2 mean aggregation of 256-dim h rows
    k_aggregate2<<<N2c, 256>>>((const float*)p_h, (const int*)p_off2,
                               (const int*)p_cnt2, (const int*)p_srt2, (float*)p_agg2);

    // layer-2 GEMM + bias + log_softmax
    k_out<<<N2c, 64>>>(Wl2, Wr2, bl2, out);
}